// round 8
// baseline (speedup 1.0000x reference)
#include <cuda_runtime.h>
#include <cuda_bf16.h>
#include <cuda_fp16.h>
#include <cstdint>

#define NN 32000
#define EE 512000
#define ET (EE + NN)
#define DD 128
#define HH 4
#define EAD 16

typedef __nv_bfloat16 bf16;

// ================= scratch =================
__device__ int   g_is64;
__device__ int   g_deg[NN];
__device__ int   g_off[NN + 1];
__device__ int   g_cur[NN];
__device__ int   g_csrc[ET];

__device__ __half g_h1h[(size_t)NN * 512];
__device__ __half g_h2h[(size_t)NN * 128];
__device__ __half g_PQh[(size_t)NN * 256];
__device__ float g_att1s[NN * 4];
__device__ float g_att1d[NN * 4];
__device__ float g_att2s[NN];
__device__ float g_att2d[NN];
__device__ float g_bePQ[256];

// bf16 split activations: [hi | lo], pitch = 2*K
__device__ bf16  g_xp [(size_t)NN * 256];
__device__ bf16  g_e1p[(size_t)NN * 1024];
__device__ bf16  g_tp [(size_t)NN * 256];
// bf16 split transposed weights: [N, 2K] = [hi | lo]
__device__ bf16  g_W1t  [512 * 256];
__device__ bf16  g_W2t  [128 * 1024];
__device__ bf16  g_Wo1t [128 * 256];
__device__ bf16  g_Wo2t [128 * 256];
__device__ bf16  g_WePQt[256 * 256];

// ================= helpers =================
__device__ __forceinline__ float lrelu02(float a) { return a > 0.f ? a : 0.2f * a; }
__device__ __forceinline__ float eluf(float v)    { return v > 0.f ? v : expm1f(v); }
__device__ __forceinline__ int idx_at(const void* ei, long pos, int is64) {
    if (is64) return (int)((const long long*)ei)[pos];
    return ((const int*)ei)[pos];
}
__device__ __forceinline__ void split_bf16(float v, bf16& h, bf16& l) {
    h = __float2bfloat16(v);
    l = __float2bfloat16(v - __bfloat162float(h));
}
__device__ __forceinline__ uint32_t smem_u32(const void* p) {
    uint32_t a;
    asm("{ .reg .u64 t; cvta.to.shared.u64 t, %1; cvt.u32.u64 %0, t; }" : "=r"(a) : "l"(p));
    return a;
}
__device__ __forceinline__ void cp_async16(uint32_t saddr, const void* g) {
    asm volatile("cp.async.cg.shared.global [%0], [%1], 16;" :: "r"(saddr), "l"(g));
}
__device__ __forceinline__ void mma_bf16(float* c, const uint32_t* a, const uint32_t* b) {
    asm volatile(
        "mma.sync.aligned.m16n8k16.row.col.f32.bf16.bf16.f32 "
        "{%0,%1,%2,%3}, {%4,%5,%6,%7}, {%8,%9}, {%0,%1,%2,%3};"
        : "+f"(c[0]), "+f"(c[1]), "+f"(c[2]), "+f"(c[3])
        : "r"(a[0]), "r"(a[1]), "r"(a[2]), "r"(a[3]), "r"(b[0]), "r"(b[1]));
}
__device__ __forceinline__ void ldm_x4(uint32_t* r, uint32_t addr) {
    asm volatile("ldmatrix.sync.aligned.m8n8.x4.shared.b16 {%0,%1,%2,%3}, [%4];"
                 : "=r"(r[0]), "=r"(r[1]), "=r"(r[2]), "=r"(r[3]) : "r"(addr));
}

// ================= fused prep: convA | convW | init =================
__global__ void k_convA_part(const float* __restrict__ src, bf16* __restrict__ dst,
                             int K, long i) {
    long m = i / K;
    int  k = (int)(i - m * K);
    bf16 h, l;
    split_bf16(src[i], h, l);
    bf16* row = dst + m * 2 * K;
    row[k] = h; row[K + k] = l;
}
__device__ __forceinline__ void conv_emit(const float* W, bf16* Wt, int K, int N, int idx) {
    int n = idx / K;
    int k = idx - n * K;
    bf16 h, l;
    split_bf16(W[(size_t)k * N + n], h, l);
    bf16* row = Wt + (size_t)n * 2 * K;
    row[k] = h; row[K + k] = l;
}
__global__ void __launch_bounds__(256) k_prep(const float* x, const int* eiw,
                                              const float* W1, const float* W2,
                                              const float* Wo1, const float* Wo2,
                                              const float* We1, const float* be1) {
    const int b = blockIdx.x, tid = threadIdx.x;
    if (b < 16000) {
        // convA: split x into g_xp
        long i = (long)b * 256 + tid;     // < 4,096,000 exactly
        long m = i >> 7;
        int  k = (int)(i & 127);
        bf16 h, l;
        split_bf16(x[i], h, l);
        bf16* row = g_xp + m * 256;
        row[k] = h; row[128 + k] = l;
    } else if (b < 16770) {
        int i = (b - 16000) * 256 + tid;
        if (i < 65536)          conv_emit(W1,  g_W1t,  128, 512, i);
        else if (i < 131072)    conv_emit(W2,  g_W2t,  512, 128, i - 65536);
        else if (i < 147456)    conv_emit(Wo1, g_Wo1t, 128, 128, i - 131072);
        else if (i < 163840)    conv_emit(Wo2, g_Wo2t, 128, 128, i - 147456);
        else if (i < 180224)    conv_emit(We1, g_WePQt, 128, 128, i - 163840);
        else if (i < 196608)    conv_emit(We1 + 128 * 128, g_WePQt + 128 * 256, 128, 128, i - 180224);
        else if (i < 196864) {
            int j = i - 196608;
            g_bePQ[j] = (j < 128) ? be1[j] : 0.f;
        }
    } else {
        // init: zero deg (125 blocks x 256 = 32000); block 16770 detects dtype
        int i = (b - 16770) * 256 + tid;
        g_deg[i] = 0;
        if (b == 16770) {
            __shared__ int s_any;
            if (tid == 0) s_any = 0;
            __syncthreads();
            int any = 0;
            for (int j = tid; j < 1024; j += 256) any |= eiw[2 * j + 1];
            if (any) atomicOr(&s_any, 1);
            __syncthreads();
            if (tid == 0) g_is64 = (s_any == 0) ? 1 : 0;
        }
    }
}

// ================= single-kernel hierarchical scan (1 block, 1024 thr) =================
__global__ void __launch_bounds__(1024) k_scan_all() {
    __shared__ int wsum[32];
    const int t = threadIdx.x, lane = t & 31, w = t >> 5;
    const int base = t * 32;
    int loc[32];
    int s = 0;
    if (base < NN) {              // threads 0..999 handle 32 contiguous each
#pragma unroll
        for (int i = 0; i < 8; i++) {
            int4 v = *(const int4*)&g_deg[base + i * 4];
            loc[i * 4 + 0] = v.x; loc[i * 4 + 1] = v.y;
            loc[i * 4 + 2] = v.z; loc[i * 4 + 3] = v.w;
            s += v.x + v.y + v.z + v.w;
        }
    }
    int inc = s;
#pragma unroll
    for (int off = 1; off < 32; off <<= 1) {
        int xx = __shfl_up_sync(0xffffffffu, inc, off);
        if (lane >= off) inc += xx;
    }
    if (lane == 31) wsum[w] = inc;
    __syncthreads();
    if (w == 0) {
        int v = wsum[lane];
        int vi = v;
#pragma unroll
        for (int off = 1; off < 32; off <<= 1) {
            int xx = __shfl_up_sync(0xffffffffu, vi, off);
            if (lane >= off) vi += xx;
        }
        wsum[lane] = vi;
    }
    __syncthreads();
    const int warpoff = (w == 0) ? 0 : wsum[w - 1];
    int run = warpoff + inc - s;      // exclusive prefix of this thread's chunk
    if (base < NN) {
#pragma unroll
        for (int i = 0; i < 32; i++) {
            g_off[base + i] = run;
            g_cur[base + i] = run;
            run += loc[i];
        }
    }
    if (t == 0) g_off[NN] = wsum[31];
}

__global__ void k_scatter(const void* ei) {
    int is64 = g_is64;
    long e = (long)blockIdx.x * blockDim.x + threadIdx.x;
    if (e >= ET) return;
    int s, d;
    if (e < EE) {
        s = idx_at(ei, e, is64);
        d = idx_at(ei, (long)EE + e, is64);
    } else {
        s = d = (int)(e - EE);
    }
    int pos = atomicAdd(&g_cur[d], 1);
    g_csrc[pos] = s;
}

// ================= mma.sync 2-term split-bf16 GEMM body, 4-stage pipeline =================
// dyn smem: 4 stages x 20480 (A 10240 | B 10240). K multiple of 64 (NT>=4).
template <int ACT, int ATT>
__device__ __forceinline__ void mgemm_body(
    const bf16* __restrict__ Ap, const bf16* __restrict__ Bp,
    int K, int Nn,
    const float* __restrict__ bias,
    float* __restrict__ Cf, __half* __restrict__ Ch,
    const float* __restrict__ a_s, const float* __restrict__ a_d,
    float* __restrict__ atts, float* __restrict__ attd,
    int heads, int head, int row0, int col0, char* dyn)
{
    __shared__ float s_as[128], s_ad[128];
    const uint32_t dynu = smem_u32(dyn);

    const int tid = threadIdx.x;
    const int wid = tid >> 5, lane = tid & 31;
    const int g = lane >> 2, tig = lane & 3;
    const int warp_m = wid & 3, warp_n = wid >> 2;
    const int K2 = 2 * K;

    const int lrow = tid >> 1, lsel = tid & 1;
    const bf16* Agb = Ap + (size_t)(row0 + lrow) * K2 + lsel * K;
    const bf16* Bgb = Bp + (size_t)(col0 + lrow) * K2 + lsel * K;
    const uint32_t soff = (uint32_t)lrow * 80u + (uint32_t)lsel * 32u;

    const int arow_l = (((lane >> 3) & 1) << 3) + (lane & 7);
    const int acol_l = (lane >> 4) << 3;
    const int brow_l = (lane & 7) + ((lane >> 4) << 3);
    const int bcol_l = ((lane >> 3) & 1) << 3;

    float c[2][8][4];
#pragma unroll
    for (int i = 0; i < 2; i++)
#pragma unroll
        for (int j = 0; j < 8; j++)
#pragma unroll
            for (int q = 0; q < 4; q++) c[i][j][q] = 0.f;

    const int NT = K >> 4;
    // prologue: issue tiles 0..2
#pragma unroll
    for (int p = 0; p < 3; p++) {
        const uint32_t st = dynu + (uint32_t)p * 20480u;
        const int koff = p * 16;
        cp_async16(st + soff, Agb + koff);
        cp_async16(st + soff + 16, Agb + koff + 8);
        cp_async16(st + 10240u + soff, Bgb + koff);
        cp_async16(st + 10240u + soff + 16, Bgb + koff + 8);
        asm volatile("cp.async.commit_group;" ::: "memory");
    }

    for (int kt = 0; kt < NT; kt++) {
        const int rem = NT - 1 - kt;
        if (rem >= 2)      asm volatile("cp.async.wait_group 2;" ::: "memory");
        else if (rem == 1) asm volatile("cp.async.wait_group 1;" ::: "memory");
        else               asm volatile("cp.async.wait_group 0;" ::: "memory");
        __syncthreads();
        if (kt + 3 < NT) {
            const uint32_t st = dynu + (uint32_t)((kt + 3) & 3) * 20480u;
            const int koff = (kt + 3) * 16;
            cp_async16(st + soff, Agb + koff);
            cp_async16(st + soff + 16, Agb + koff + 8);
            cp_async16(st + 10240u + soff, Bgb + koff);
            cp_async16(st + 10240u + soff + 16, Bgb + koff + 8);
            asm volatile("cp.async.commit_group;" ::: "memory");
        }

        const uint32_t aBase = dynu + (uint32_t)(kt & 3) * 20480u;
        const uint32_t bBase = aBase + 10240u;

        uint32_t ah[2][4], al[2][4], bb[8][2];
#pragma unroll
        for (int mi = 0; mi < 2; mi++) {
            uint32_t r = aBase + (uint32_t)(warp_m * 32 + mi * 16 + arow_l) * 80u
                               + (uint32_t)acol_l * 2u;
            ldm_x4(ah[mi], r);
            ldm_x4(al[mi], r + 32u);
        }
#pragma unroll
        for (int p = 0; p < 4; p++) {
            uint32_t t[4];
            uint32_t r = bBase + (uint32_t)(warp_n * 64 + p * 16 + brow_l) * 80u
                               + (uint32_t)bcol_l * 2u;
            ldm_x4(t, r);
            bb[2 * p][0] = t[0]; bb[2 * p][1] = t[1];
            bb[2 * p + 1][0] = t[2]; bb[2 * p + 1][1] = t[3];
        }
#pragma unroll
        for (int mi = 0; mi < 2; mi++)
#pragma unroll
            for (int ni = 0; ni < 8; ni++)
                mma_bf16(c[mi][ni], ah[mi], bb[ni]);
#pragma unroll
        for (int mi = 0; mi < 2; mi++)
#pragma unroll
            for (int ni = 0; ni < 8; ni++)
                mma_bf16(c[mi][ni], al[mi], bb[ni]);
#pragma unroll
        for (int p = 0; p < 4; p++) {
            uint32_t t[4];
            uint32_t r = bBase + (uint32_t)(warp_n * 64 + p * 16 + brow_l) * 80u
                               + (uint32_t)bcol_l * 2u + 32u;
            ldm_x4(t, r);
            bb[2 * p][0] = t[0]; bb[2 * p][1] = t[1];
            bb[2 * p + 1][0] = t[2]; bb[2 * p + 1][1] = t[3];
        }
#pragma unroll
        for (int mi = 0; mi < 2; mi++)
#pragma unroll
            for (int ni = 0; ni < 8; ni++)
                mma_bf16(c[mi][ni], ah[mi], bb[ni]);
    }

    if (ATT) {
        __syncthreads();
        if (tid < 128) { s_as[tid] = 0.f; s_ad[tid] = 0.f; }
        __syncthreads();
    }

    float ssv[2][2] = {{0.f, 0.f}, {0.f, 0.f}};
    float sdv[2][2] = {{0.f, 0.f}, {0.f, 0.f}};

#pragma unroll
    for (int ni = 0; ni < 8; ni++) {
        const int cA = col0 + warp_n * 64 + ni * 8 + tig * 2;
        float b0 = 0.f, b1 = 0.f;
        if (bias) { b0 = __ldg(&bias[cA]); b1 = __ldg(&bias[cA + 1]); }
        float asA = 0.f, asB = 0.f, adA = 0.f, adB = 0.f;
        if (ATT) {
            asA = __ldg(&a_s[cA]); asB = __ldg(&a_s[cA + 1]);
            adA = __ldg(&a_d[cA]); adB = __ldg(&a_d[cA + 1]);
        }
#pragma unroll
        for (int mi = 0; mi < 2; mi++) {
            const int r0g = row0 + warp_m * 32 + mi * 16 + g;
            const int r1g = r0g + 8;
            float v00 = c[mi][ni][0] + b0, v01 = c[mi][ni][1] + b1;
            float v10 = c[mi][ni][2] + b0, v11 = c[mi][ni][3] + b1;
            if (ACT == 1) {
                v00 = fmaxf(v00, 0.f); v01 = fmaxf(v01, 0.f);
                v10 = fmaxf(v10, 0.f); v11 = fmaxf(v11, 0.f);
            }
            if (ATT) {
                ssv[mi][0] += v00 * asA + v01 * asB;
                ssv[mi][1] += v10 * asA + v11 * asB;
                sdv[mi][0] += v00 * adA + v01 * adB;
                sdv[mi][1] += v10 * adA + v11 * adB;
            }
            if (Cf) {
                *(float2*)&Cf[(size_t)r0g * Nn + cA] = make_float2(v00, v01);
                *(float2*)&Cf[(size_t)r1g * Nn + cA] = make_float2(v10, v11);
            }
            if (Ch) {
                *(__half2*)&Ch[(size_t)r0g * Nn + cA] = __floats2half2_rn(v00, v01);
                *(__half2*)&Ch[(size_t)r1g * Nn + cA] = __floats2half2_rn(v10, v11);
            }
        }
    }

    if (ATT) {
#pragma unroll
        for (int mi = 0; mi < 2; mi++) {
            const int rl0 = warp_m * 32 + mi * 16 + g;
            atomicAdd(&s_as[rl0], ssv[mi][0]);
            atomicAdd(&s_as[rl0 + 8], ssv[mi][1]);
            atomicAdd(&s_ad[rl0], sdv[mi][0]);
            atomicAdd(&s_ad[rl0 + 8], sdv[mi][1]);
        }
        __syncthreads();
        if (tid < 128) {
            const int row = row0 + tid;
            atts[row * heads + head] = s_as[tid];
            attd[row * heads + head] = s_ad[tid];
        }
    }
}

// ================= fused main1: gemm1 (1000 blocks) | hist (2125 blocks) =================
__global__ void __launch_bounds__(256) k_main1(const void* __restrict__ ei,
                                               const float* __restrict__ as1,
                                               const float* __restrict__ ad1) {
    extern __shared__ char dyn[];
    const int b = blockIdx.x;
    if (b < 1000) {
        const int row0 = (b >> 2) * 128;
        const int col0 = (b & 3) * 128;
        mgemm_body<0, 2>(g_xp, g_W1t, 128, 512, nullptr,
                         nullptr, g_h1h, as1, ad1, g_att1s, g_att1d,
                         4, b & 3, row0, col0, dyn);
    } else {
        const int is64 = g_is64;
        long e = (long)(b - 1000) * 256 + threadIdx.x;   // < ET exactly
        int d = (e < EE) ? idx_at(ei, (long)EE + e, is64) : (int)(e - EE);
        atomicAdd(&g_deg[d], 1);
    }
}

// ================= gemm2 =================
__global__ void __launch_bounds__(256) k_mgemm2(const float* __restrict__ as2,
                                                const float* __restrict__ ad2) {
    extern __shared__ char dyn[];
    mgemm_body<0, 1>(g_e1p, g_W2t, 512, 128, nullptr,
                     nullptr, g_h2h, as2, ad2, g_att2s, g_att2d,
                     1, 0, blockIdx.x * 128, 0, dyn);
}

// ================= fused node MLP (2-stage pipeline, A in smem between stages) ======
template <int AFROM>
__device__ __forceinline__ void gemm_stage(
    float (&c)[2][8][4],
    const bf16* Agb, const bf16* Bgb,
    uint32_t aChunkBase, uint32_t sAs, uint32_t sBs, uint32_t soff,
    int warp_m, int warp_n, int arow_l, int acol_l, int brow_l, int bcol_l)
{
#pragma unroll
    for (int i = 0; i < 2; i++)
#pragma unroll
        for (int j = 0; j < 8; j++)
#pragma unroll
            for (int q = 0; q < 4; q++) c[i][j][q] = 0.f;

    if (AFROM == 0) { cp_async16(sAs + soff, Agb); cp_async16(sAs + soff + 16, Agb + 8); }
    cp_async16(sBs + soff, Bgb);
    cp_async16(sBs + soff + 16, Bgb + 8);
    asm volatile("cp.async.commit_group;" ::: "memory");

#pragma unroll
    for (int kt = 0; kt < 8; kt++) {
        const int buf = kt & 1;
        if (kt + 1 < 8) {
            const int koff = (kt + 1) * 16;
            const uint32_t bofs = ((kt + 1) & 1) ? 10240u : 0u;
            if (AFROM == 0) {
                cp_async16(sAs + bofs + soff, Agb + koff);
                cp_async16(sAs + bofs + soff + 16, Agb + koff + 8);
            }
            cp_async16(sBs + bofs + soff, Bgb + koff);
            cp_async16(sBs + bofs + soff + 16, Bgb + koff + 8);
            asm volatile("cp.async.commit_group;" ::: "memory");
            asm volatile("cp.async.wait_group 1;" ::: "memory");
        } else {
            asm volatile("cp.async.wait_group 0;" ::: "memory");
        }
        __syncthreads();
        const uint32_t aBase = (AFROM == 0) ? (sAs + (uint32_t)buf * 10240u)
                                            : (aChunkBase + (uint32_t)kt * 10240u);
        const uint32_t bBase = sBs + (uint32_t)buf * 10240u;

        uint32_t ah[2][4], al[2][4], bb[8][2];
#pragma unroll
        for (int mi = 0; mi < 2; mi++) {
            uint32_t r = aBase + (uint32_t)(warp_m * 32 + mi * 16 + arow_l) * 80u
                               + (uint32_t)acol_l * 2u;
            ldm_x4(ah[mi], r);
            ldm_x4(al[mi], r + 32u);
        }
#pragma unroll
        for (int p = 0; p < 4; p++) {
            uint32_t t[4];
            uint32_t r = bBase + (uint32_t)(warp_n * 64 + p * 16 + brow_l) * 80u
                               + (uint32_t)bcol_l * 2u;
            ldm_x4(t, r);
            bb[2 * p][0] = t[0]; bb[2 * p][1] = t[1];
            bb[2 * p + 1][0] = t[2]; bb[2 * p + 1][1] = t[3];
        }
#pragma unroll
        for (int mi = 0; mi < 2; mi++)
#pragma unroll
            for (int ni = 0; ni < 8; ni++)
                mma_bf16(c[mi][ni], ah[mi], bb[ni]);
#pragma unroll
        for (int mi = 0; mi < 2; mi++)
#pragma unroll
            for (int ni = 0; ni < 8; ni++)
                mma_bf16(c[mi][ni], al[mi], bb[ni]);
#pragma unroll
        for (int p = 0; p < 4; p++) {
            uint32_t t[4];
            uint32_t r = bBase + (uint32_t)(warp_n * 64 + p * 16 + brow_l) * 80u
                               + (uint32_t)bcol_l * 2u + 32u;
            ldm_x4(t, r);
            bb[2 * p][0] = t[0]; bb[2 * p][1] = t[1];
            bb[2 * p + 1][0] = t[2]; bb[2 * p + 1][1] = t[3];
        }
#pragma unroll
        for (int mi = 0; mi < 2; mi++)
#pragma unroll
            for (int ni = 0; ni < 8; ni++)
                mma_bf16(c[mi][ni], ah[mi], bb[ni]);
        __syncthreads();
    }
}

__device__ __forceinline__ void store_split(char* base, int row, int col, float v0, float v1) {
    bf16 h0, l0, h1, l1;
    split_bf16(v0, h0, l0);
    split_bf16(v1, h1, l1);
    char* p = base + (col >> 4) * 10240 + row * 80 + (col & 15) * 2;
    __nv_bfloat162 hp, lp;
    hp.x = h0; hp.y = h1; lp.x = l0; lp.y = l1;
    *(__nv_bfloat162*)p = hp;
    *(__nv_bfloat162*)(p + 32) = lp;
}

__global__ void __launch_bounds__(256) k_nodeMLP(const float* __restrict__ bo1,
                                                 const float* __restrict__ bo2,
                                                 float* __restrict__ xo,
                                                 __half* __restrict__ PQh) {
    extern __shared__ char dyn[];
    char* uspC = dyn;
    char* xspC = dyn + 81920;
    const uint32_t dynu = smem_u32(dyn);
    const uint32_t uspU = dynu;
    const uint32_t xspU = dynu + 81920u;
    const uint32_t sAs  = dynu + 163840u;
    const uint32_t sBs  = dynu + 184320u;

    const int tid = threadIdx.x;
    const int wid = tid >> 5, lane = tid & 31;
    const int g = lane >> 2, tig = lane & 3;
    const int warp_m = wid & 3, warp_n = wid >> 2;
    const int row0 = blockIdx.x * 128;
    const int lrow = tid >> 1, lsel = tid & 1;
    const uint32_t soff = (uint32_t)lrow * 80u + (uint32_t)lsel * 32u;
    const int arow_l = (((lane >> 3) & 1) << 3) + (lane & 7);
    const int acol_l = (lane >> 4) << 3;
    const int brow_l = (lane & 7) + ((lane >> 4) << 3);
    const int bcol_l = ((lane >> 3) & 1) << 3;

    float c[2][8][4];

    {
        const bf16* Agb = g_tp + (size_t)(row0 + lrow) * 256 + lsel * 128;
        const bf16* Bgb = g_Wo1t + (size_t)lrow * 256 + lsel * 128;
        gemm_stage<0>(c, Agb, Bgb, 0u, sAs, sBs, soff,
                      warp_m, warp_n, arow_l, acol_l, brow_l, bcol_l);
#pragma unroll
        for (int ni = 0; ni < 8; ni++) {
            const int col = warp_n * 64 + ni * 8 + tig * 2;
            const float b0 = __ldg(&bo1[col]), b1 = __ldg(&bo1[col + 1]);
#pragma unroll
            for (int mi = 0; mi < 2; mi++) {
                const int r0l = warp_m * 32 + mi * 16 + g;
                store_split(uspC, r0l, col,
                            fmaxf(c[mi][ni][0] + b0, 0.f), fmaxf(c[mi][ni][1] + b1, 0.f));
                store_split(uspC, r0l + 8, col,
                            fmaxf(c[mi][ni][2] + b0, 0.f), fmaxf(c[mi][ni][3] + b1, 0.f));
            }
        }
        __syncthreads();
    }

    {
        const bf16* Bgb = g_Wo2t + (size_t)lrow * 256 + lsel * 128;
        gemm_stage<1>(c, nullptr, Bgb, uspU, sAs, sBs, soff,
                      warp_m, warp_n, arow_l, acol_l, brow_l, bcol_l);
#pragma unroll
        for (int ni = 0; ni < 8; ni++) {
            const int col = warp_n * 64 + ni * 8 + tig * 2;
            const float b0 = __ldg(&bo2[col]), b1 = __ldg(&bo2[col + 1]);
#pragma unroll
            for (int mi = 0; mi < 2; mi++) {
                const int r0l = warp_m * 32 + mi * 16 + g;
                const int r1l = r0l + 8;
                float v00 = c[mi][ni][0] + b0, v01 = c[mi][ni][1] + b1;
                float v10 = c[mi][ni][2] + b0, v11 = c[mi][ni][3] + b1;
                *(float2*)&xo[(size_t)(row0 + r0l) * 128 + col] = make_float2(v00, v01);
                *(float2*)&xo[(size_t)(row0 + r1l) * 128 + col] = make_float2(v10, v11);
                store_split(xspC, r0l, col, v00, v01);
                store_split(xspC, r1l, col, v10, v11);
            }
        }
        __syncthreads();
    }

#pragma unroll
    for (int p = 0; p < 2; p++) {
        const bf16* Bgb = g_WePQt + (size_t)(p * 128 + lrow) * 256 + lsel * 128;
        gemm_stage<1>(c, nullptr, Bgb, xspU, sAs, sBs, soff,
                      warp_m, warp_n, arow_l, acol_l, brow_l, bcol_l);
#pragma unroll
        for (int ni = 0; ni < 8; ni++) {
            const int col = warp_n * 64 + ni * 8 + tig * 2;
            const int gcol = p * 128 + col;
            const float b0 = g_bePQ[gcol], b1 = g_bePQ[gcol + 1];
#pragma unroll
            for (int mi = 0; mi < 2; mi++) {
                const int r0g = row0 + warp_m * 32 + mi * 16 + g;
                const int r1g = r0g + 8;
                *(__half2*)&PQh[(size_t)r0g * 256 + gcol] =
                    __floats2half2_rn(c[mi][ni][0] + b0, c[mi][ni][1] + b1);
                *(__half2*)&PQh[(size_t)r1g * 256 + gcol] =
                    __floats2half2_rn(c[mi][ni][2] + b0, c[mi][ni][3] + b1);
            }
        }
    }
}

// ================= layer-1 aggregation (one-pass) =================
__global__ void __launch_bounds__(128) k_agg1(const float* __restrict__ b1) {
    const int n = blockIdx.x, tid = threadIdx.x;
    const int h = tid >> 5;
    const int beg = g_off[n], end = g_off[n + 1];

    __shared__ float s_ex[128 * 4];
    __shared__ int   s_s[128];

    const float4 ad = *(const float4*)&g_att1d[n * 4];

    float4 acc = make_float4(0.f, 0.f, 0.f, 0.f);
    float den = 0.f;
    for (int c0 = beg; c0 < end; c0 += 128) {
        int mcnt = min(128, end - c0);
        if (tid < mcnt) {
            int s = g_csrc[c0 + tid];
            s_s[tid] = s;
            float4 as = *(const float4*)&g_att1s[s * 4];
            s_ex[tid * 4 + 0] = expf(lrelu02(as.x + ad.x));
            s_ex[tid * 4 + 1] = expf(lrelu02(as.y + ad.y));
            s_ex[tid * 4 + 2] = expf(lrelu02(as.z + ad.z));
            s_ex[tid * 4 + 3] = expf(lrelu02(as.w + ad.w));
        }
        __syncthreads();
        for (int j = 0; j < mcnt; j++) {
            float w = s_ex[j * 4 + h];
            den += w;
            uint2 hv2 = *(const uint2*)&g_h1h[(size_t)s_s[j] * 512 + tid * 4];
            float2 f01 = __half22float2(*(const __half2*)&hv2.x);
            float2 f23 = __half22float2(*(const __half2*)&hv2.y);
            acc.x += f01.x * w; acc.y += f01.y * w;
            acc.z += f23.x * w; acc.w += f23.y * w;
        }
        __syncthreads();
    }
    const float invden = 1.f / den;
    float4 bv = *(const float4*)&b1[tid * 4];
    float o0 = eluf(acc.x * invden + bv.x), o1 = eluf(acc.y * invden + bv.y);
    float o2 = eluf(acc.z * invden + bv.z), o3 = eluf(acc.w * invden + bv.w);
    bf16 h0, l0, h1b, l1, h2b, l2, h3b, l3;
    split_bf16(o0, h0, l0); split_bf16(o1, h1b, l1);
    split_bf16(o2, h2b, l2); split_bf16(o3, h3b, l3);
    __nv_bfloat162 hA, hB, lA, lB;
    hA.x = h0; hA.y = h1b; hB.x = h2b; hB.y = h3b;
    lA.x = l0; lA.y = l1;  lB.x = l2;  lB.y = l3;
    const size_t rb = (size_t)n * 1024;
    const int cb = tid * 4;
    *(__nv_bfloat162*)&g_e1p[rb + cb]           = hA;
    *(__nv_bfloat162*)&g_e1p[rb + cb + 2]       = hB;
    *(__nv_bfloat162*)&g_e1p[rb + 512 + cb]     = lA;
    *(__nv_bfloat162*)&g_e1p[rb + 512 + cb + 2] = lB;
}

// ================= layer-2 aggregation (one-pass) =================
__global__ void __launch_bounds__(128) k_agg2(const float* __restrict__ b2) {
    const int n = blockIdx.x, tid = threadIdx.x;
    const int beg = g_off[n], end = g_off[n + 1];

    __shared__ float s_ex[128];
    __shared__ int   s_s[128];

    const float adn = g_att2d[n];

    float acc = 0.f, den = 0.f;
    for (int c0 = beg; c0 < end; c0 += 128) {
        int mcnt = min(128, end - c0);
        if (tid < mcnt) {
            int s = g_csrc[c0 + tid];
            s_s[tid] = s;
            s_ex[tid] = expf(lrelu02(g_att2s[s] + adn));
        }
        __syncthreads();
        for (int j = 0; j < mcnt; j++) {
            float w = s_ex[j];
            den += w;
            acc += __half2float(g_h2h[(size_t)s_s[j] * 128 + tid]) * w;
        }
        __syncthreads();
    }
    float o = eluf(acc / den + b2[tid]);
    bf16 h, l;
    split_bf16(o, h, l);
    g_tp[(size_t)n * 256 + tid]       = h;
    g_tp[(size_t)n * 256 + 128 + tid] = l;
}

// ================= fused edge MLP =================
__global__ void __launch_bounds__(256) k_edge_final(const void* __restrict__ ei,
                                                    const float* __restrict__ eattr,
                                                    const float* __restrict__ We1,
                                                    const float* __restrict__ We2,
                                                    const float* __restrict__ be2,
                                                    float* __restrict__ out) {
    __shared__ float sW1[16 * 128];
    __shared__ float sW2[128 * 16];
    __shared__ float sHid[8][128];
    const int tid = threadIdx.x;
    for (int i = tid; i < 2048; i += 256) {
        sW1[i] = We1[256 * 128 + i];
        sW2[i] = We2[i];
    }
    const int is64 = g_is64;
    __syncthreads();

    const int warp = tid >> 5, lane = tid & 31;
    const long e = (long)blockIdx.x * 8 + warp;
    if (e < EE) {
        int s = idx_at(ei, e, is64);
        int d = idx_at(ei, (long)EE + e, is64);
        uint2 pv = *(const uint2*)&g_PQh[(size_t)s * 256 + lane * 4];
        uint2 qv = *(const uint2*)&g_PQh[(size_t)d * 256 + 128 + lane * 4];
        float2 pa = __half22float2(*(const __half2*)&pv.x);
        float2 pb = __half22float2(*(const __half2*)&pv.y);
        float2 qa = __half22float2(*(const __half2*)&qv.x);
        float2 qb = __half22float2(*(const __half2*)&qv.y);
        float4 hv;
        hv.x = pa.x + qa.x; hv.y = pa.y + qa.y;
        hv.z = pb.x + qb.x; hv.w = pb.y + qb.y;
        float eav = (lane < 16) ? eattr[e * 16 + lane] : 0.f;
#pragma unroll
        for (int k = 0; k < 16; k++) {
            float ek = __shfl_sync(0xffffffffu, eav, k);
            float4 wv = *(const float4*)&sW1[k * 128 + lane * 4];
            hv.x += ek * wv.x; hv.y += ek * wv.y;
            hv.z += ek * wv.z; hv.w += ek * wv.w;
        }
        hv.x = fmaxf(hv.x, 0.f); hv.y = fmaxf(hv.y, 0.f);
        hv.z = fmaxf(hv.z, 0.f); hv.w = fmaxf(hv.w, 0.f);
        *(float4*)&sHid[warp][lane * 4] = hv;
    }
    __syncwarp();
    if (e < EE) {
        const int o = lane & 15, half = lane >> 4;
        float acc = 0.f;
#pragma unroll
        for (int c = 0; c < 64; c++) {
            int cc = half + 2 * c;
            acc += sHid[warp][cc] * sW2[cc * 16 + o];
        }
        acc += __shfl_xor_sync(0xffffffffu, acc, 16);
        if (lane < 16) out[e * 16 + lane] = acc + be2[lane];
    }
}

// ================= launcher =================
extern "C" void kernel_launch(void* const* d_in, const int* in_sizes, int n_in,
                              void* d_out, int out_size) {
    const float* x    = (const float*)d_in[0];
    const void*  ei   = d_in[1];
    const float* eatt = (const float*)d_in[2];
    const float* W1   = (const float*)d_in[3];
    const float* as1  = (const float*)d_in[4];
    const float* ad1  = (const float*)d_in[5];
    const float* b1   = (const float*)d_in[6];
    const float* W2   = (const float*)d_in[7];
    const float* as2  = (const float*)d_in[8];
    const float* ad2  = (const float*)d_in[9];
    const float* b2   = (const float*)d_in[10];
    const float* Wo1  = (const float*)d_in[11];
    const float* bo1  = (const float*)d_in[12];
    const float* Wo2  = (const float*)d_in[13];
    const float* bo2  = (const float*)d_in[14];
    const float* We1  = (const float*)d_in[15];
    const float* be1  = (const float*)d_in[16];
    const float* We2  = (const float*)d_in[17];
    const float* be2  = (const float*)d_in[18];

    float* out  = (float*)d_out;
    float* xo   = out;
    float* eout = out + (size_t)NN * 128;

    __half *PQh;
    cudaGetSymbolAddress((void**)&PQh, g_PQh);

    cudaFuncSetAttribute(k_main1, cudaFuncAttributeMaxDynamicSharedMemorySize, 81920);
    cudaFuncSetAttribute(k_mgemm2, cudaFuncAttributeMaxDynamicSharedMemorySize, 81920);
    cudaFuncSetAttribute(k_nodeMLP, cudaFuncAttributeMaxDynamicSharedMemorySize, 204800);

    // 0: prep = convA | convW | init
    k_prep<<<16895, 256>>>(x, (const int*)ei, W1, W2, Wo1, Wo2, We1, be1);
    // 1: gemm1 | hist (independent, overlapped in one launch)
    k_main1<<<1000 + 2125, 256, 81920>>>(ei, as1, ad1);
    // 2: scan (single block)
    k_scan_all<<<1, 1024>>>();
    // 3: scatter
    k_scatter<<<2125, 256>>>(ei);
    // 4: layer-1 aggregate
    k_agg1<<<NN, 128>>>(b1);
    // 5: gemm2
    k_mgemm2<<<250, 256, 81920>>>(as2, ad2);
    // 6: layer-2 aggregate
    k_agg2<<<NN, 128>>>(b2);
    // 7: node MLP (t -> u -> xo -> PQ)
    k_nodeMLP<<<250, 256, 204800>>>(bo1, bo2, xo, PQh);
    // 8: edge MLP
    k_edge_final<<<EE / 8, 256>>>(ei, eatt, We1, We2, be2, eout);
}

// round 9
// speedup vs baseline: 1.4808x; 1.4808x over previous
#include <cuda_runtime.h>
#include <cuda_bf16.h>
#include <cuda_fp16.h>
#include <cstdint>

#define NN 32000
#define EE 512000
#define ET (EE + NN)
#define DD 128
#define HH 4
#define EAD 16

typedef __nv_bfloat16 bf16;

// ================= scratch =================
__device__ int   g_is64;
__device__ int   g_deg[NN];
__device__ int   g_off[NN + 1];
__device__ int   g_cur[NN];
__device__ int   g_csrc[ET];

__device__ __half g_h1h[(size_t)NN * 512];
__device__ __half g_h2h[(size_t)NN * 128];
__device__ __half g_PQh[(size_t)NN * 256];
__device__ float g_att1s[NN * 4];
__device__ float g_att1d[NN * 4];
__device__ float g_att2s[NN];
__device__ float g_att2d[NN];
__device__ float g_bePQ[256];

// bf16 split activations: [hi | lo], pitch = 2*K
__device__ bf16  g_xp [(size_t)NN * 256];
__device__ bf16  g_e1p[(size_t)NN * 1024];
__device__ bf16  g_tp [(size_t)NN * 256];
// bf16 split transposed weights: [N, 2K] = [hi | lo]
__device__ bf16  g_W1t  [512 * 256];
__device__ bf16  g_W2t  [128 * 1024];
__device__ bf16  g_Wo1t [128 * 256];
__device__ bf16  g_Wo2t [128 * 256];
__device__ bf16  g_WePQt[256 * 256];

// ================= helpers =================
__device__ __forceinline__ float lrelu02(float a) { return a > 0.f ? a : 0.2f * a; }
__device__ __forceinline__ float eluf(float v)    { return v > 0.f ? v : expm1f(v); }
__device__ __forceinline__ int idx_at(const void* ei, long pos, int is64) {
    if (is64) return (int)((const long long*)ei)[pos];
    return ((const int*)ei)[pos];
}
__device__ __forceinline__ void split_bf16(float v, bf16& h, bf16& l) {
    h = __float2bfloat16(v);
    l = __float2bfloat16(v - __bfloat162float(h));
}
__device__ __forceinline__ uint32_t smem_u32(const void* p) {
    uint32_t a;
    asm("{ .reg .u64 t; cvta.to.shared.u64 t, %1; cvt.u32.u64 %0, t; }" : "=r"(a) : "l"(p));
    return a;
}
__device__ __forceinline__ void cp_async16(uint32_t saddr, const void* g) {
    asm volatile("cp.async.cg.shared.global [%0], [%1], 16;" :: "r"(saddr), "l"(g));
}
__device__ __forceinline__ void mma_bf16(float* c, const uint32_t* a, const uint32_t* b) {
    asm volatile(
        "mma.sync.aligned.m16n8k16.row.col.f32.bf16.bf16.f32 "
        "{%0,%1,%2,%3}, {%4,%5,%6,%7}, {%8,%9}, {%0,%1,%2,%3};"
        : "+f"(c[0]), "+f"(c[1]), "+f"(c[2]), "+f"(c[3])
        : "r"(a[0]), "r"(a[1]), "r"(a[2]), "r"(a[3]), "r"(b[0]), "r"(b[1]));
}
__device__ __forceinline__ void mma_f16(float* c, const uint32_t* a, const uint32_t* b) {
    asm volatile(
        "mma.sync.aligned.m16n8k16.row.col.f32.f16.f16.f32 "
        "{%0,%1,%2,%3}, {%4,%5,%6,%7}, {%8,%9}, {%0,%1,%2,%3};"
        : "+f"(c[0]), "+f"(c[1]), "+f"(c[2]), "+f"(c[3])
        : "r"(a[0]), "r"(a[1]), "r"(a[2]), "r"(a[3]), "r"(b[0]), "r"(b[1]));
}
__device__ __forceinline__ void ldm_x4(uint32_t* r, uint32_t addr) {
    asm volatile("ldmatrix.sync.aligned.m8n8.x4.shared.b16 {%0,%1,%2,%3}, [%4];"
                 : "=r"(r[0]), "=r"(r[1]), "=r"(r[2]), "=r"(r[3]) : "r"(addr));
}

// ================= fused prep: convA | convW | init =================
__device__ __forceinline__ void conv_emit(const float* W, bf16* Wt, int K, int N, int idx) {
    int n = idx / K;
    int k = idx - n * K;
    bf16 h, l;
    split_bf16(W[(size_t)k * N + n], h, l);
    bf16* row = Wt + (size_t)n * 2 * K;
    row[k] = h; row[K + k] = l;
}
__global__ void __launch_bounds__(256) k_prep(const float* x, const int* eiw,
                                              const float* W1, const float* W2,
                                              const float* Wo1, const float* Wo2,
                                              const float* We1, const float* be1) {
    const int b = blockIdx.x, tid = threadIdx.x;
    if (b < 16000) {
        long i = (long)b * 256 + tid;
        long m = i >> 7;
        int  k = (int)(i & 127);
        bf16 h, l;
        split_bf16(x[i], h, l);
        bf16* row = g_xp + m * 256;
        row[k] = h; row[128 + k] = l;
    } else if (b < 16770) {
        int i = (b - 16000) * 256 + tid;
        if (i < 65536)          conv_emit(W1,  g_W1t,  128, 512, i);
        else if (i < 131072)    conv_emit(W2,  g_W2t,  512, 128, i - 65536);
        else if (i < 147456)    conv_emit(Wo1, g_Wo1t, 128, 128, i - 131072);
        else if (i < 163840)    conv_emit(Wo2, g_Wo2t, 128, 128, i - 147456);
        else if (i < 180224)    conv_emit(We1, g_WePQt, 128, 128, i - 163840);
        else if (i < 196608)    conv_emit(We1 + 128 * 128, g_WePQt + 128 * 256, 128, 128, i - 180224);
        else if (i < 196864) {
            int j = i - 196608;
            g_bePQ[j] = (j < 128) ? be1[j] : 0.f;
        }
    } else {
        int i = (b - 16770) * 256 + tid;
        g_deg[i] = 0;
        if (b == 16770) {
            __shared__ int s_any;
            if (tid == 0) s_any = 0;
            __syncthreads();
            int any = 0;
            for (int j = tid; j < 1024; j += 256) any |= eiw[2 * j + 1];
            if (any) atomicOr(&s_any, 1);
            __syncthreads();
            if (tid == 0) g_is64 = (s_any == 0) ? 1 : 0;
        }
    }
}

// ================= CSR =================
__global__ void k_hist(const void* ei) {
    int is64 = g_is64;
    long e = (long)blockIdx.x * 256 + threadIdx.x;   // grid 2125 x 256 = ET exactly
    int d = (e < EE) ? idx_at(ei, (long)EE + e, is64) : (int)(e - EE);
    atomicAdd(&g_deg[d], 1);
}
__global__ void __launch_bounds__(1024) k_scan_all() {
    __shared__ int wsum[32];
    const int t = threadIdx.x, lane = t & 31, w = t >> 5;
    const int base = t * 32;
    int loc[32];
    int s = 0;
    if (base < NN) {
#pragma unroll
        for (int i = 0; i < 8; i++) {
            int4 v = *(const int4*)&g_deg[base + i * 4];
            loc[i * 4 + 0] = v.x; loc[i * 4 + 1] = v.y;
            loc[i * 4 + 2] = v.z; loc[i * 4 + 3] = v.w;
            s += v.x + v.y + v.z + v.w;
        }
    }
    int inc = s;
#pragma unroll
    for (int off = 1; off < 32; off <<= 1) {
        int xx = __shfl_up_sync(0xffffffffu, inc, off);
        if (lane >= off) inc += xx;
    }
    if (lane == 31) wsum[w] = inc;
    __syncthreads();
    if (w == 0) {
        int v = wsum[lane];
        int vi = v;
#pragma unroll
        for (int off = 1; off < 32; off <<= 1) {
            int xx = __shfl_up_sync(0xffffffffu, vi, off);
            if (lane >= off) vi += xx;
        }
        wsum[lane] = vi;
    }
    __syncthreads();
    const int warpoff = (w == 0) ? 0 : wsum[w - 1];
    int run = warpoff + inc - s;
    if (base < NN) {
#pragma unroll
        for (int i = 0; i < 32; i++) {
            g_off[base + i] = run;
            g_cur[base + i] = run;
            run += loc[i];
        }
    }
    if (t == 0) g_off[NN] = wsum[31];
}
__global__ void k_scatter(const void* ei) {
    int is64 = g_is64;
    long e = (long)blockIdx.x * 256 + threadIdx.x;
    int s, d;
    if (e < EE) {
        s = idx_at(ei, e, is64);
        d = idx_at(ei, (long)EE + e, is64);
    } else {
        s = d = (int)(e - EE);
    }
    int pos = atomicAdd(&g_cur[d], 1);
    g_csrc[pos] = s;
}

// ================= mma.sync 2-term split-bf16 GEMM body, 4-stage pipeline =================
template <int ACT, int ATT>
__device__ __forceinline__ void mgemm_body(
    const bf16* __restrict__ Ap, const bf16* __restrict__ Bp,
    int K, int Nn,
    const float* __restrict__ bias,
    float* __restrict__ Cf, __half* __restrict__ Ch,
    const float* __restrict__ a_s, const float* __restrict__ a_d,
    float* __restrict__ atts, float* __restrict__ attd,
    int heads, int head, int row0, int col0, char* dyn)
{
    __shared__ float s_as[128], s_ad[128];
    const uint32_t dynu = smem_u32(dyn);

    const int tid = threadIdx.x;
    const int wid = tid >> 5, lane = tid & 31;
    const int g = lane >> 2, tig = lane & 3;
    const int warp_m = wid & 3, warp_n = wid >> 2;
    const int K2 = 2 * K;

    const int lrow = tid >> 1, lsel = tid & 1;
    const bf16* Agb = Ap + (size_t)(row0 + lrow) * K2 + lsel * K;
    const bf16* Bgb = Bp + (size_t)(col0 + lrow) * K2 + lsel * K;
    const uint32_t soff = (uint32_t)lrow * 80u + (uint32_t)lsel * 32u;

    const int arow_l = (((lane >> 3) & 1) << 3) + (lane & 7);
    const int acol_l = (lane >> 4) << 3;
    const int brow_l = (lane & 7) + ((lane >> 4) << 3);
    const int bcol_l = ((lane >> 3) & 1) << 3;

    float c[2][8][4];
#pragma unroll
    for (int i = 0; i < 2; i++)
#pragma unroll
        for (int j = 0; j < 8; j++)
#pragma unroll
            for (int q = 0; q < 4; q++) c[i][j][q] = 0.f;

    const int NT = K >> 4;
#pragma unroll
    for (int p = 0; p < 3; p++) {
        const uint32_t st = dynu + (uint32_t)p * 20480u;
        const int koff = p * 16;
        cp_async16(st + soff, Agb + koff);
        cp_async16(st + soff + 16, Agb + koff + 8);
        cp_async16(st + 10240u + soff, Bgb + koff);
        cp_async16(st + 10240u + soff + 16, Bgb + koff + 8);
        asm volatile("cp.async.commit_group;" ::: "memory");
    }

    for (int kt = 0; kt < NT; kt++) {
        const int rem = NT - 1 - kt;
        if (rem >= 2)      asm volatile("cp.async.wait_group 2;" ::: "memory");
        else if (rem == 1) asm volatile("cp.async.wait_group 1;" ::: "memory");
        else               asm volatile("cp.async.wait_group 0;" ::: "memory");
        __syncthreads();
        if (kt + 3 < NT) {
            const uint32_t st = dynu + (uint32_t)((kt + 3) & 3) * 20480u;
            const int koff = (kt + 3) * 16;
            cp_async16(st + soff, Agb + koff);
            cp_async16(st + soff + 16, Agb + koff + 8);
            cp_async16(st + 10240u + soff, Bgb + koff);
            cp_async16(st + 10240u + soff + 16, Bgb + koff + 8);
            asm volatile("cp.async.commit_group;" ::: "memory");
        }

        const uint32_t aBase = dynu + (uint32_t)(kt & 3) * 20480u;
        const uint32_t bBase = aBase + 10240u;

        uint32_t ah[2][4], al[2][4], bb[8][2];
#pragma unroll
        for (int mi = 0; mi < 2; mi++) {
            uint32_t r = aBase + (uint32_t)(warp_m * 32 + mi * 16 + arow_l) * 80u
                               + (uint32_t)acol_l * 2u;
            ldm_x4(ah[mi], r);
            ldm_x4(al[mi], r + 32u);
        }
#pragma unroll
        for (int p = 0; p < 4; p++) {
            uint32_t t[4];
            uint32_t r = bBase + (uint32_t)(warp_n * 64 + p * 16 + brow_l) * 80u
                               + (uint32_t)bcol_l * 2u;
            ldm_x4(t, r);
            bb[2 * p][0] = t[0]; bb[2 * p][1] = t[1];
            bb[2 * p + 1][0] = t[2]; bb[2 * p + 1][1] = t[3];
        }
#pragma unroll
        for (int mi = 0; mi < 2; mi++)
#pragma unroll
            for (int ni = 0; ni < 8; ni++)
                mma_bf16(c[mi][ni], ah[mi], bb[ni]);
#pragma unroll
        for (int mi = 0; mi < 2; mi++)
#pragma unroll
            for (int ni = 0; ni < 8; ni++)
                mma_bf16(c[mi][ni], al[mi], bb[ni]);
#pragma unroll
        for (int p = 0; p < 4; p++) {
            uint32_t t[4];
            uint32_t r = bBase + (uint32_t)(warp_n * 64 + p * 16 + brow_l) * 80u
                               + (uint32_t)bcol_l * 2u + 32u;
            ldm_x4(t, r);
            bb[2 * p][0] = t[0]; bb[2 * p][1] = t[1];
            bb[2 * p + 1][0] = t[2]; bb[2 * p + 1][1] = t[3];
        }
#pragma unroll
        for (int mi = 0; mi < 2; mi++)
#pragma unroll
            for (int ni = 0; ni < 8; ni++)
                mma_bf16(c[mi][ni], ah[mi], bb[ni]);
    }

    if (ATT) {
        __syncthreads();
        if (tid < 128) { s_as[tid] = 0.f; s_ad[tid] = 0.f; }
        __syncthreads();
    }

    float ssv[2][2] = {{0.f, 0.f}, {0.f, 0.f}};
    float sdv[2][2] = {{0.f, 0.f}, {0.f, 0.f}};

#pragma unroll
    for (int ni = 0; ni < 8; ni++) {
        const int cA = col0 + warp_n * 64 + ni * 8 + tig * 2;
        float b0 = 0.f, b1 = 0.f;
        if (bias) { b0 = __ldg(&bias[cA]); b1 = __ldg(&bias[cA + 1]); }
        float asA = 0.f, asB = 0.f, adA = 0.f, adB = 0.f;
        if (ATT) {
            asA = __ldg(&a_s[cA]); asB = __ldg(&a_s[cA + 1]);
            adA = __ldg(&a_d[cA]); adB = __ldg(&a_d[cA + 1]);
        }
#pragma unroll
        for (int mi = 0; mi < 2; mi++) {
            const int r0g = row0 + warp_m * 32 + mi * 16 + g;
            const int r1g = r0g + 8;
            float v00 = c[mi][ni][0] + b0, v01 = c[mi][ni][1] + b1;
            float v10 = c[mi][ni][2] + b0, v11 = c[mi][ni][3] + b1;
            if (ACT == 1) {
                v00 = fmaxf(v00, 0.f); v01 = fmaxf(v01, 0.f);
                v10 = fmaxf(v10, 0.f); v11 = fmaxf(v11, 0.f);
            }
            if (ATT) {
                ssv[mi][0] += v00 * asA + v01 * asB;
                ssv[mi][1] += v10 * asA + v11 * asB;
                sdv[mi][0] += v00 * adA + v01 * adB;
                sdv[mi][1] += v10 * adA + v11 * adB;
            }
            if (Cf) {
                *(float2*)&Cf[(size_t)r0g * Nn + cA] = make_float2(v00, v01);
                *(float2*)&Cf[(size_t)r1g * Nn + cA] = make_float2(v10, v11);
            }
            if (Ch) {
                *(__half2*)&Ch[(size_t)r0g * Nn + cA] = __floats2half2_rn(v00, v01);
                *(__half2*)&Ch[(size_t)r1g * Nn + cA] = __floats2half2_rn(v10, v11);
            }
        }
    }

    if (ATT) {
#pragma unroll
        for (int mi = 0; mi < 2; mi++) {
            const int rl0 = warp_m * 32 + mi * 16 + g;
            atomicAdd(&s_as[rl0], ssv[mi][0]);
            atomicAdd(&s_as[rl0 + 8], ssv[mi][1]);
            atomicAdd(&s_ad[rl0], sdv[mi][0]);
            atomicAdd(&s_ad[rl0 + 8], sdv[mi][1]);
        }
        __syncthreads();
        if (tid < 128) {
            const int row = row0 + tid;
            atts[row * heads + head] = s_as[tid];
            attd[row * heads + head] = s_ad[tid];
        }
    }
}

__global__ void __launch_bounds__(256) k_mgemm1(const float* __restrict__ as1,
                                                const float* __restrict__ ad1) {
    extern __shared__ char dyn[];
    const int b = blockIdx.x;
    mgemm_body<0, 2>(g_xp, g_W1t, 128, 512, nullptr,
                     nullptr, g_h1h, as1, ad1, g_att1s, g_att1d,
                     4, b & 3, (b >> 2) * 128, (b & 3) * 128, dyn);
}
__global__ void __launch_bounds__(256) k_mgemm2(const float* __restrict__ as2,
                                                const float* __restrict__ ad2) {
    extern __shared__ char dyn[];
    mgemm_body<0, 1>(g_e1p, g_W2t, 512, 128, nullptr,
                     nullptr, g_h2h, as2, ad2, g_att2s, g_att2d,
                     1, 0, blockIdx.x * 128, 0, dyn);
}

// ================= fused node MLP (2-stage pipeline, A in smem between stages) ======
template <int AFROM>
__device__ __forceinline__ void gemm_stage(
    float (&c)[2][8][4],
    const bf16* Agb, const bf16* Bgb,
    uint32_t aChunkBase, uint32_t sAs, uint32_t sBs, uint32_t soff,
    int warp_m, int warp_n, int arow_l, int acol_l, int brow_l, int bcol_l)
{
#pragma unroll
    for (int i = 0; i < 2; i++)
#pragma unroll
        for (int j = 0; j < 8; j++)
#pragma unroll
            for (int q = 0; q < 4; q++) c[i][j][q] = 0.f;

    if (AFROM == 0) { cp_async16(sAs + soff, Agb); cp_async16(sAs + soff + 16, Agb + 8); }
    cp_async16(sBs + soff, Bgb);
    cp_async16(sBs + soff + 16, Bgb + 8);
    asm volatile("cp.async.commit_group;" ::: "memory");

#pragma unroll
    for (int kt = 0; kt < 8; kt++) {
        const int buf = kt & 1;
        if (kt + 1 < 8) {
            const int koff = (kt + 1) * 16;
            const uint32_t bofs = ((kt + 1) & 1) ? 10240u : 0u;
            if (AFROM == 0) {
                cp_async16(sAs + bofs + soff, Agb + koff);
                cp_async16(sAs + bofs + soff + 16, Agb + koff + 8);
            }
            cp_async16(sBs + bofs + soff, Bgb + koff);
            cp_async16(sBs + bofs + soff + 16, Bgb + koff + 8);
            asm volatile("cp.async.commit_group;" ::: "memory");
            asm volatile("cp.async.wait_group 1;" ::: "memory");
        } else {
            asm volatile("cp.async.wait_group 0;" ::: "memory");
        }
        __syncthreads();
        const uint32_t aBase = (AFROM == 0) ? (sAs + (uint32_t)buf * 10240u)
                                            : (aChunkBase + (uint32_t)kt * 10240u);
        const uint32_t bBase = sBs + (uint32_t)buf * 10240u;

        uint32_t ah[2][4], al[2][4], bb[8][2];
#pragma unroll
        for (int mi = 0; mi < 2; mi++) {
            uint32_t r = aBase + (uint32_t)(warp_m * 32 + mi * 16 + arow_l) * 80u
                               + (uint32_t)acol_l * 2u;
            ldm_x4(ah[mi], r);
            ldm_x4(al[mi], r + 32u);
        }
#pragma unroll
        for (int p = 0; p < 4; p++) {
            uint32_t t[4];
            uint32_t r = bBase + (uint32_t)(warp_n * 64 + p * 16 + brow_l) * 80u
                               + (uint32_t)bcol_l * 2u;
            ldm_x4(t, r);
            bb[2 * p][0] = t[0]; bb[2 * p][1] = t[1];
            bb[2 * p + 1][0] = t[2]; bb[2 * p + 1][1] = t[3];
        }
#pragma unroll
        for (int mi = 0; mi < 2; mi++)
#pragma unroll
            for (int ni = 0; ni < 8; ni++)
                mma_bf16(c[mi][ni], ah[mi], bb[ni]);
#pragma unroll
        for (int mi = 0; mi < 2; mi++)
#pragma unroll
            for (int ni = 0; ni < 8; ni++)
                mma_bf16(c[mi][ni], al[mi], bb[ni]);
#pragma unroll
        for (int p = 0; p < 4; p++) {
            uint32_t t[4];
            uint32_t r = bBase + (uint32_t)(warp_n * 64 + p * 16 + brow_l) * 80u
                               + (uint32_t)bcol_l * 2u + 32u;
            ldm_x4(t, r);
            bb[2 * p][0] = t[0]; bb[2 * p][1] = t[1];
            bb[2 * p + 1][0] = t[2]; bb[2 * p + 1][1] = t[3];
        }
#pragma unroll
        for (int mi = 0; mi < 2; mi++)
#pragma unroll
            for (int ni = 0; ni < 8; ni++)
                mma_bf16(c[mi][ni], ah[mi], bb[ni]);
        __syncthreads();
    }
}

__device__ __forceinline__ void store_split(char* base, int row, int col, float v0, float v1) {
    bf16 h0, l0, h1, l1;
    split_bf16(v0, h0, l0);
    split_bf16(v1, h1, l1);
    char* p = base + (col >> 4) * 10240 + row * 80 + (col & 15) * 2;
    __nv_bfloat162 hp, lp;
    hp.x = h0; hp.y = h1; lp.x = l0; lp.y = l1;
    *(__nv_bfloat162*)p = hp;
    *(__nv_bfloat162*)(p + 32) = lp;
}

__global__ void __launch_bounds__(256) k_nodeMLP(const float* __restrict__ bo1,
                                                 const float* __restrict__ bo2,
                                                 float* __restrict__ xo,
                                                 __half* __restrict__ PQh) {
    extern __shared__ char dyn[];
    char* uspC = dyn;
    char* xspC = dyn + 81920;
    const uint32_t dynu = smem_u32(dyn);
    const uint32_t uspU = dynu;
    const uint32_t xspU = dynu + 81920u;
    const uint32_t sAs  = dynu + 163840u;
    const uint32_t sBs  = dynu + 184320u;

    const int tid = threadIdx.x;
    const int wid = tid >> 5, lane = tid & 31;
    const int g = lane >> 2, tig = lane & 3;
    const int warp_m = wid & 3, warp_n = wid >> 2;
    const int row0 = blockIdx.x * 128;
    const int lrow = tid >> 1, lsel = tid & 1;
    const uint32_t soff = (uint32_t)lrow * 80u + (uint32_t)lsel * 32u;
    const int arow_l = (((lane >> 3) & 1) << 3) + (lane & 7);
    const int acol_l = (lane >> 4) << 3;
    const int brow_l = (lane & 7) + ((lane >> 4) << 3);
    const int bcol_l = ((lane >> 3) & 1) << 3;

    float c[2][8][4];

    {
        const bf16* Agb = g_tp + (size_t)(row0 + lrow) * 256 + lsel * 128;
        const bf16* Bgb = g_Wo1t + (size_t)lrow * 256 + lsel * 128;
        gemm_stage<0>(c, Agb, Bgb, 0u, sAs, sBs, soff,
                      warp_m, warp_n, arow_l, acol_l, brow_l, bcol_l);
#pragma unroll
        for (int ni = 0; ni < 8; ni++) {
            const int col = warp_n * 64 + ni * 8 + tig * 2;
            const float b0 = __ldg(&bo1[col]), b1 = __ldg(&bo1[col + 1]);
#pragma unroll
            for (int mi = 0; mi < 2; mi++) {
                const int r0l = warp_m * 32 + mi * 16 + g;
                store_split(uspC, r0l, col,
                            fmaxf(c[mi][ni][0] + b0, 0.f), fmaxf(c[mi][ni][1] + b1, 0.f));
                store_split(uspC, r0l + 8, col,
                            fmaxf(c[mi][ni][2] + b0, 0.f), fmaxf(c[mi][ni][3] + b1, 0.f));
            }
        }
        __syncthreads();
    }

    {
        const bf16* Bgb = g_Wo2t + (size_t)lrow * 256 + lsel * 128;
        gemm_stage<1>(c, nullptr, Bgb, uspU, sAs, sBs, soff,
                      warp_m, warp_n, arow_l, acol_l, brow_l, bcol_l);
#pragma unroll
        for (int ni = 0; ni < 8; ni++) {
            const int col = warp_n * 64 + ni * 8 + tig * 2;
            const float b0 = __ldg(&bo2[col]), b1 = __ldg(&bo2[col + 1]);
#pragma unroll
            for (int mi = 0; mi < 2; mi++) {
                const int r0l = warp_m * 32 + mi * 16 + g;
                const int r1l = r0l + 8;
                float v00 = c[mi][ni][0] + b0, v01 = c[mi][ni][1] + b1;
                float v10 = c[mi][ni][2] + b0, v11 = c[mi][ni][3] + b1;
                *(float2*)&xo[(size_t)(row0 + r0l) * 128 + col] = make_float2(v00, v01);
                *(float2*)&xo[(size_t)(row0 + r1l) * 128 + col] = make_float2(v10, v11);
                store_split(xspC, r0l, col, v00, v01);
                store_split(xspC, r1l, col, v10, v11);
            }
        }
        __syncthreads();
    }

#pragma unroll
    for (int p = 0; p < 2; p++) {
        const bf16* Bgb = g_WePQt + (size_t)(p * 128 + lrow) * 256 + lsel * 128;
        gemm_stage<1>(c, nullptr, Bgb, xspU, sAs, sBs, soff,
                      warp_m, warp_n, arow_l, acol_l, brow_l, bcol_l);
#pragma unroll
        for (int ni = 0; ni < 8; ni++) {
            const int col = warp_n * 64 + ni * 8 + tig * 2;
            const int gcol = p * 128 + col;
            const float b0 = g_bePQ[gcol], b1 = g_bePQ[gcol + 1];
#pragma unroll
            for (int mi = 0; mi < 2; mi++) {
                const int r0g = row0 + warp_m * 32 + mi * 16 + g;
                const int r1g = r0g + 8;
                *(__half2*)&PQh[(size_t)r0g * 256 + gcol] =
                    __floats2half2_rn(c[mi][ni][0] + b0, c[mi][ni][1] + b1);
                *(__half2*)&PQh[(size_t)r1g * 256 + gcol] =
                    __floats2half2_rn(c[mi][ni][2] + b0, c[mi][ni][3] + b1);
            }
        }
    }
}

// ================= layer-1 aggregation (one-pass) =================
__global__ void __launch_bounds__(128) k_agg1(const float* __restrict__ b1) {
    const int n = blockIdx.x, tid = threadIdx.x;
    const int h = tid >> 5;
    const int beg = g_off[n], end = g_off[n + 1];

    __shared__ float s_ex[128 * 4];
    __shared__ int   s_s[128];

    const float4 ad = *(const float4*)&g_att1d[n * 4];

    float4 acc = make_float4(0.f, 0.f, 0.f, 0.f);
    float den = 0.f;
    for (int c0 = beg; c0 < end; c0 += 128) {
        int mcnt = min(128, end - c0);
        if (tid < mcnt) {
            int s = g_csrc[c0 + tid];
            s_s[tid] = s;
            float4 as = *(const float4*)&g_att1s[s * 4];
            s_ex[tid * 4 + 0] = expf(lrelu02(as.x + ad.x));
            s_ex[tid * 4 + 1] = expf(lrelu02(as.y + ad.y));
            s_ex[tid * 4 + 2] = expf(lrelu02(as.z + ad.z));
            s_ex[tid * 4 + 3] = expf(lrelu02(as.w + ad.w));
        }
        __syncthreads();
        for (int j = 0; j < mcnt; j++) {
            float w = s_ex[j * 4 + h];
            den += w;
            uint2 hv2 = *(const uint2*)&g_h1h[(size_t)s_s[j] * 512 + tid * 4];
            float2 f01 = __half22float2(*(const __half2*)&hv2.x);
            float2 f23 = __half22float2(*(const __half2*)&hv2.y);
            acc.x += f01.x * w; acc.y += f01.y * w;
            acc.z += f23.x * w; acc.w += f23.y * w;
        }
        __syncthreads();
    }
    const float invden = 1.f / den;
    float4 bv = *(const float4*)&b1[tid * 4];
    float o0 = eluf(acc.x * invden + bv.x), o1 = eluf(acc.y * invden + bv.y);
    float o2 = eluf(acc.z * invden + bv.z), o3 = eluf(acc.w * invden + bv.w);
    bf16 h0, l0, h1b, l1, h2b, l2, h3b, l3;
    split_bf16(o0, h0, l0); split_bf16(o1, h1b, l1);
    split_bf16(o2, h2b, l2); split_bf16(o3, h3b, l3);
    __nv_bfloat162 hA, hB, lA, lB;
    hA.x = h0; hA.y = h1b; hB.x = h2b; hB.y = h3b;
    lA.x = l0; lA.y = l1;  lB.x = l2;  lB.y = l3;
    const size_t rb = (size_t)n * 1024;
    const int cb = tid * 4;
    *(__nv_bfloat162*)&g_e1p[rb + cb]           = hA;
    *(__nv_bfloat162*)&g_e1p[rb + cb + 2]       = hB;
    *(__nv_bfloat162*)&g_e1p[rb + 512 + cb]     = lA;
    *(__nv_bfloat162*)&g_e1p[rb + 512 + cb + 2] = lB;
}

// ================= layer-2 aggregation (one-pass) =================
__global__ void __launch_bounds__(128) k_agg2(const float* __restrict__ b2) {
    const int n = blockIdx.x, tid = threadIdx.x;
    const int beg = g_off[n], end = g_off[n + 1];

    __shared__ float s_ex[128];
    __shared__ int   s_s[128];

    const float adn = g_att2d[n];

    float acc = 0.f, den = 0.f;
    for (int c0 = beg; c0 < end; c0 += 128) {
        int mcnt = min(128, end - c0);
        if (tid < mcnt) {
            int s = g_csrc[c0 + tid];
            s_s[tid] = s;
            s_ex[tid] = expf(lrelu02(g_att2s[s] + adn));
        }
        __syncthreads();
        for (int j = 0; j < mcnt; j++) {
            float w = s_ex[j];
            den += w;
            acc += __half2float(g_h2h[(size_t)s_s[j] * 128 + tid]) * w;
        }
        __syncthreads();
    }
    float o = eluf(acc / den + b2[tid]);
    bf16 h, l;
    split_bf16(o, h, l);
    g_tp[(size_t)n * 256 + tid]       = h;
    g_tp[(size_t)n * 256 + 128 + tid] = l;
}

// ================= edge MLP v2: reg-W1 phase1 + fp16 mma phase2 =================
// block = 256 thr, 64 edges. Stage A: warp w -> hidden rows w*8..w*8+7 (fp16 smem).
// Stage B: warps 0..3 -> m16n16k128 mma on rows 16t..16t+15.
__global__ void __launch_bounds__(256) k_edge_final(const void* __restrict__ ei,
                                                    const float* __restrict__ eattr,
                                                    const float* __restrict__ We1,
                                                    const float* __restrict__ We2,
                                                    const float* __restrict__ be2,
                                                    float* __restrict__ out) {
    __shared__ float  sW1f[16 * 128];
    __shared__ __half sHid[64][136];
    __shared__ __half sW2h[16][136];
    const int tid = threadIdx.x, wid = tid >> 5, lane = tid & 31;

    for (int i = tid; i < 2048; i += 256) {
        sW1f[i] = We1[256 * 128 + i];
        int cc = i >> 4, o = i & 15;          // We2 is [128][16]
        sW2h[o][cc] = __float2half(We2[i]);
    }
    __syncthreads();

    // per-lane W1 registers (16 x float4)
    float4 w1r[16];
#pragma unroll
    for (int k = 0; k < 16; k++) w1r[k] = *(const float4*)&sW1f[k * 128 + lane * 4];

    const int is64 = g_is64;
    const long e0 = (long)blockIdx.x * 64;

    // stage A
#pragma unroll
    for (int r = 0; r < 8; r++) {
        const long e = e0 + wid * 8 + r;
        int s = idx_at(ei, e, is64);
        int d = idx_at(ei, (long)EE + e, is64);
        uint2 pv = *(const uint2*)&g_PQh[(size_t)s * 256 + lane * 4];
        uint2 qv = *(const uint2*)&g_PQh[(size_t)d * 256 + 128 + lane * 4];
        float2 pa = __half22float2(*(const __half2*)&pv.x);
        float2 pb = __half22float2(*(const __half2*)&pv.y);
        float2 qa = __half22float2(*(const __half2*)&qv.x);
        float2 qb = __half22float2(*(const __half2*)&qv.y);
        float4 hv;
        hv.x = pa.x + qa.x; hv.y = pa.y + qa.y;
        hv.z = pb.x + qb.x; hv.w = pb.y + qb.y;
        float eav = (lane < 16) ? eattr[e * 16 + lane] : 0.f;
#pragma unroll
        for (int k = 0; k < 16; k++) {
            float ek = __shfl_sync(0xffffffffu, eav, k);
            hv.x += ek * w1r[k].x; hv.y += ek * w1r[k].y;
            hv.z += ek * w1r[k].z; hv.w += ek * w1r[k].w;
        }
        __half2 h01 = __floats2half2_rn(fmaxf(hv.x, 0.f), fmaxf(hv.y, 0.f));
        __half2 h23 = __floats2half2_rn(fmaxf(hv.z, 0.f), fmaxf(hv.w, 0.f));
        uint2 packed;
        packed.x = *(uint32_t*)&h01;
        packed.y = *(uint32_t*)&h23;
        *(uint2*)&sHid[wid * 8 + r][lane * 4] = packed;
    }
    __syncthreads();

    // stage B: 4 mma warps
    if (wid < 4) {
        const int g = lane >> 2, tig = lane & 3;
        const int arow_l = (((lane >> 3) & 1) << 3) + (lane & 7);
        const int acol_l = (lane >> 4) << 3;
        const int brow_l = (lane & 7) + ((lane >> 4) << 3);
        const int bcol_l = ((lane >> 3) & 1) << 3;
        const uint32_t sA = smem_u32(&sHid[wid * 16][0]);
        const uint32_t sB = smem_u32(&sW2h[0][0]);

        float c0[4] = {0.f, 0.f, 0.f, 0.f};
        float c1[4] = {0.f, 0.f, 0.f, 0.f};
#pragma unroll
        for (int kk = 0; kk < 128; kk += 16) {
            uint32_t af[4], bfr[4];
            ldm_x4(af, sA + (uint32_t)arow_l * 272u + (uint32_t)(kk + acol_l) * 2u);
            ldm_x4(bfr, sB + (uint32_t)brow_l * 272u + (uint32_t)(kk + bcol_l) * 2u);
            mma_f16(c0, af, bfr);          // n-rows 0..7
            mma_f16(c1, af, bfr + 2);      // n-rows 8..15
        }

        const long eA = e0 + wid * 16 + g;
        const long eB = eA + 8;
        const float b0 = __ldg(&be2[tig * 2]),     b1 = __ldg(&be2[tig * 2 + 1]);
        const float b8 = __ldg(&be2[8 + tig * 2]), b9 = __ldg(&be2[8 + tig * 2 + 1]);
        *(float2*)&out[eA * 16 + tig * 2]     = make_float2(c0[0] + b0, c0[1] + b1);
        *(float2*)&out[eB * 16 + tig * 2]     = make_float2(c0[2] + b0, c0[3] + b1);
        *(float2*)&out[eA * 16 + 8 + tig * 2] = make_float2(c1[0] + b8, c1[1] + b9);
        *(float2*)&out[eB * 16 + 8 + tig * 2] = make_float2(c1[2] + b8, c1[3] + b9);
    }
}

// ================= launcher =================
extern "C" void kernel_launch(void* const* d_in, const int* in_sizes, int n_in,
                              void* d_out, int out_size) {
    const float* x    = (const float*)d_in[0];
    const void*  ei   = d_in[1];
    const float* eatt = (const float*)d_in[2];
    const float* W1   = (const float*)d_in[3];
    const float* as1  = (const float*)d_in[4];
    const float* ad1  = (const float*)d_in[5];
    const float* b1   = (const float*)d_in[6];
    const float* W2   = (const float*)d_in[7];
    const float* as2  = (const float*)d_in[8];
    const float* ad2  = (const float*)d_in[9];
    const float* b2   = (const float*)d_in[10];
    const float* Wo1  = (const float*)d_in[11];
    const float* bo1  = (const float*)d_in[12];
    const float* Wo2  = (const float*)d_in[13];
    const float* bo2  = (const float*)d_in[14];
    const float* We1  = (const float*)d_in[15];
    const float* be1  = (const float*)d_in[16];
    const float* We2  = (const float*)d_in[17];
    const float* be2  = (const float*)d_in[18];

    float* out  = (float*)d_out;
    float* xo   = out;
    float* eout = out + (size_t)NN * 128;

    __half* PQh;
    cudaGetSymbolAddress((void**)&PQh, g_PQh);

    cudaFuncSetAttribute(k_mgemm1, cudaFuncAttributeMaxDynamicSharedMemorySize, 81920);
    cudaFuncSetAttribute(k_mgemm2, cudaFuncAttributeMaxDynamicSharedMemorySize, 81920);
    cudaFuncSetAttribute(k_nodeMLP, cudaFuncAttributeMaxDynamicSharedMemorySize, 204800);

    // 0: prep = convA | convW | init
    k_prep<<<16895, 256>>>(x, (const int*)ei, W1, W2, Wo1, Wo2, We1, be1);
    // 1: hist
    k_hist<<<2125, 256>>>(ei);
    // 2: scan
    k_scan_all<<<1, 1024>>>();
    // 3: gemm1 (profiled slot)
    k_mgemm1<<<1000, 256, 81920>>>(as1, ad1);
    // 4: scatter
    k_scatter<<<2125, 256>>>(ei);
    // 5: agg1
    k_agg1<<<NN, 128>>>(b1);
    // 6: gemm2
    k_mgemm2<<<250, 256, 81920>>>(as2, ad2);
    // 7: agg2
    k_agg2<<<NN, 128>>>(b2);
    // 8: node MLP
    k_nodeMLP<<<250, 256, 204800>>>(bo1, bo2, xo, PQh);
    // 9: edge MLP v2
    k_edge_final<<<EE / 64, 256>>>(ei, eatt, We1, We2, be2, eout);
}